// round 8
// baseline (speedup 1.0000x reference)
#include <cuda_runtime.h>
#include <cuda_bf16.h>

#define NNODES 100000
#define NEDGES 600000
#define DFEAT  128

// Scratch
__device__ float g_dis[NNODES];    // deg -> rsqrt(deg)
__device__ float g_s[NNODES];      // raw dot products x·w
__device__ float g_p[NNODES];      // p0 = dis * s
__device__ float g_acc[NNODES];    // round-1 accumulator
__device__ float g_p2[NNODES];     // p1 = dis^2 * acc1
__device__ float g_acc2[NNODES];   // round-2 accumulator

// fused-kernel grid layout: count blocks first, then dot blocks
#define CNT_THREADS ((NEDGES / 4))            // 150000 threads, 4 edges each
#define CNT_BLOCKS  ((CNT_THREADS + 255) / 256)          // 586
#define DOT_BLOCKS  ((NNODES / 4 + 7) / 8)               // 8 warps/block, 4 nodes/warp = 3125

// K1: deg = 1 (self loop)
__global__ void k_init() {
    int i = blockIdx.x * blockDim.x + threadIdx.x;
    if (i < NNODES) g_dis[i] = 1.0f;
}

// K2 (fused): blocks [0, CNT_BLOCKS) count degrees (L2-atomic-bound);
//             blocks [CNT_BLOCKS, ...) compute s = x·w (HBM-bound).
// Independent work -> overlapped execution.
__global__ void k_dot_count(const float* __restrict__ x,
                            const float* __restrict__ w,
                            const int* __restrict__ ei) {
    if (blockIdx.x < CNT_BLOCKS) {
        int t = blockIdx.x * blockDim.x + threadIdx.x;
        int e = t * 4;
        if (e < NEDGES) {
            int4 c4 = *reinterpret_cast<const int4*>(ei + NEDGES + e);
            atomicAdd(&g_dis[c4.x], 1.0f);
            atomicAdd(&g_dis[c4.y], 1.0f);
            atomicAdd(&g_dis[c4.z], 1.0f);
            atomicAdd(&g_dis[c4.w], 1.0f);
        }
        return;
    }

    int warp_id = ((blockIdx.x - CNT_BLOCKS) * blockDim.x + threadIdx.x) >> 5;
    int lane = threadIdx.x & 31;
    int base = warp_id * 4;
    if (base >= NNODES) return;   // NNODES % 4 == 0

    const float4* wr = reinterpret_cast<const float4*>(w);
    float4 wv = __ldg(&wr[lane]);

    float4 xv0 = reinterpret_cast<const float4*>(x + (size_t)(base + 0) * DFEAT)[lane];
    float4 xv1 = reinterpret_cast<const float4*>(x + (size_t)(base + 1) * DFEAT)[lane];
    float4 xv2 = reinterpret_cast<const float4*>(x + (size_t)(base + 2) * DFEAT)[lane];
    float4 xv3 = reinterpret_cast<const float4*>(x + (size_t)(base + 3) * DFEAT)[lane];

    float s0 = xv0.x * wv.x + xv0.y * wv.y + xv0.z * wv.z + xv0.w * wv.w;
    float s1 = xv1.x * wv.x + xv1.y * wv.y + xv1.z * wv.z + xv1.w * wv.w;
    float s2 = xv2.x * wv.x + xv2.y * wv.y + xv2.z * wv.z + xv2.w * wv.w;
    float s3 = xv3.x * wv.x + xv3.y * wv.y + xv3.z * wv.z + xv3.w * wv.w;

    #pragma unroll
    for (int off = 16; off > 0; off >>= 1) {
        s0 += __shfl_xor_sync(0xFFFFFFFFu, s0, off);
        s1 += __shfl_xor_sync(0xFFFFFFFFu, s1, off);
        s2 += __shfl_xor_sync(0xFFFFFFFFu, s2, off);
        s3 += __shfl_xor_sync(0xFFFFFFFFu, s3, off);
    }

    if (lane == 0) {
        *reinterpret_cast<float4*>(&g_s[base]) = make_float4(s0, s1, s2, s3);
    }
}

// K3: dis = rsqrt(deg); p0 = dis*s; acc1 init = p0 (self-loop term)
__global__ void k_norm() {
    int i = blockIdx.x * blockDim.x + threadIdx.x;
    if (i < NNODES) {
        float d = rsqrtf(g_dis[i]);
        g_dis[i] = d;
        float p = d * g_s[i];
        g_p[i]   = p;
        g_acc[i] = p;
    }
}

// K4: round-1 edges: acc1[col] += p0[row]; 4 edges/thread, int4 index loads
__global__ void k_edge1(const int* __restrict__ ei) {
    int e = (blockIdx.x * blockDim.x + threadIdx.x) * 4;
    if (e < NEDGES) {
        int4 r4 = *reinterpret_cast<const int4*>(ei + e);
        int4 c4 = *reinterpret_cast<const int4*>(ei + NEDGES + e);
        float pa = __ldg(&g_p[r4.x]);
        float pb = __ldg(&g_p[r4.y]);
        float pc = __ldg(&g_p[r4.z]);
        float pd = __ldg(&g_p[r4.w]);
        atomicAdd(&g_acc[c4.x], pa);
        atomicAdd(&g_acc[c4.y], pb);
        atomicAdd(&g_acc[c4.z], pc);
        atomicAdd(&g_acc[c4.w], pd);
    }
}

// K5: p1 = dis^2 * acc1 ; acc2 init = p1
__global__ void k_pre2() {
    int i = blockIdx.x * blockDim.x + threadIdx.x;
    if (i < NNODES) {
        float dd = g_dis[i];
        float v = dd * dd * g_acc[i];
        g_p2[i]   = v;
        g_acc2[i] = v;
    }
}

// K6: round-2 edges: acc2[col] += p1[row]
__global__ void k_edge2(const int* __restrict__ ei) {
    int e = (blockIdx.x * blockDim.x + threadIdx.x) * 4;
    if (e < NEDGES) {
        int4 r4 = *reinterpret_cast<const int4*>(ei + e);
        int4 c4 = *reinterpret_cast<const int4*>(ei + NEDGES + e);
        float pa = __ldg(&g_p2[r4.x]);
        float pb = __ldg(&g_p2[r4.y]);
        float pc = __ldg(&g_p2[r4.z]);
        float pd = __ldg(&g_p2[r4.w]);
        atomicAdd(&g_acc2[c4.x], pa);
        atomicAdd(&g_acc2[c4.y], pb);
        atomicAdd(&g_acc2[c4.z], pc);
        atomicAdd(&g_acc2[c4.w], pd);
    }
}

// K7: out = dis * acc2 + b
__global__ void k_post(float* __restrict__ out, const float* __restrict__ b) {
    int i = blockIdx.x * blockDim.x + threadIdx.x;
    if (i < NNODES) {
        out[i] = g_dis[i] * g_acc2[i] + b[0];
    }
}

extern "C" void kernel_launch(void* const* d_in, const int* in_sizes, int n_in,
                              void* d_out, int out_size) {
    const float* x  = (const float*)d_in[0];
    const int*   ei = (const int*)d_in[1];
    const float* W  = (const float*)d_in[2];
    const float* b  = (const float*)d_in[3];
    float* out = (float*)d_out;

    const int T = 256;
    const int gN  = (NNODES + T - 1) / T;
    const int gE4 = (NEDGES / 4 + T - 1) / T;

    k_init<<<gN, T>>>();
    k_dot_count<<<CNT_BLOCKS + DOT_BLOCKS, T>>>(x, W, ei);
    k_norm<<<gN, T>>>();
    k_edge1<<<gE4, T>>>(ei);
    k_pre2<<<gN, T>>>();
    k_edge2<<<gE4, T>>>(ei);
    k_post<<<gN, T>>>(out, b);
}

// round 9
// speedup vs baseline: 1.1725x; 1.1725x over previous
#include <cuda_runtime.h>
#include <cuda_bf16.h>

#define NNODES 100000
#define NEDGES 600000
#define DFEAT  128

// Scratch
__device__ float g_dis[NNODES];    // deg -> rsqrt(deg)
__device__ float g_p[NNODES];      // p0 = dis * (x·w)
__device__ float g_acc[NNODES];    // round-1 accumulator (init = p0)
__device__ float g_p2[NNODES];     // p1 = dis^2 * acc1
__device__ float g_acc2[NNODES];   // round-2 accumulator (init = p1)

// K1: deg = 1 (self loop)
__global__ void k_init() {
    int i = blockIdx.x * blockDim.x + threadIdx.x;
    if (i < NNODES) g_dis[i] = 1.0f;
}

// K2: degree count, 2 edges/thread (high warp supply for atomic latency hiding)
__global__ void k_count_deg(const int* __restrict__ ei) {
    int e = (blockIdx.x * blockDim.x + threadIdx.x) * 2;
    if (e < NEDGES) {
        int2 c2 = *reinterpret_cast<const int2*>(ei + NEDGES + e);
        atomicAdd(&g_dis[c2.x], 1.0f);
        atomicAdd(&g_dis[c2.y], 1.0f);
    }
}

// K3: dis = rsqrt(deg); s = x·w per node (4 nodes/warp, MLP=4);
//     p0 = dis*s; acc1 init = p0 (self-loop term)
__global__ void k_dot(const float* __restrict__ x, const float* __restrict__ w) {
    int warp_id = (blockIdx.x * blockDim.x + threadIdx.x) >> 5;
    int lane = threadIdx.x & 31;
    int base = warp_id * 4;
    if (base >= NNODES) return;   // NNODES % 4 == 0

    float d = 0.0f;
    if (lane < 4) {
        d = rsqrtf(g_dis[base + lane]);
        g_dis[base + lane] = d;
    }

    const float4* wr = reinterpret_cast<const float4*>(w);
    float4 wv = __ldg(&wr[lane]);

    float4 xv0 = reinterpret_cast<const float4*>(x + (size_t)(base + 0) * DFEAT)[lane];
    float4 xv1 = reinterpret_cast<const float4*>(x + (size_t)(base + 1) * DFEAT)[lane];
    float4 xv2 = reinterpret_cast<const float4*>(x + (size_t)(base + 2) * DFEAT)[lane];
    float4 xv3 = reinterpret_cast<const float4*>(x + (size_t)(base + 3) * DFEAT)[lane];

    float s0 = xv0.x * wv.x + xv0.y * wv.y + xv0.z * wv.z + xv0.w * wv.w;
    float s1 = xv1.x * wv.x + xv1.y * wv.y + xv1.z * wv.z + xv1.w * wv.w;
    float s2 = xv2.x * wv.x + xv2.y * wv.y + xv2.z * wv.z + xv2.w * wv.w;
    float s3 = xv3.x * wv.x + xv3.y * wv.y + xv3.z * wv.z + xv3.w * wv.w;

    #pragma unroll
    for (int off = 16; off > 0; off >>= 1) {
        s0 += __shfl_xor_sync(0xFFFFFFFFu, s0, off);
        s1 += __shfl_xor_sync(0xFFFFFFFFu, s1, off);
        s2 += __shfl_xor_sync(0xFFFFFFFFu, s2, off);
        s3 += __shfl_xor_sync(0xFFFFFFFFu, s3, off);
    }

    float d0 = __shfl_sync(0xFFFFFFFFu, d, 0);
    float d1 = __shfl_sync(0xFFFFFFFFu, d, 1);
    float d2 = __shfl_sync(0xFFFFFFFFu, d, 2);
    float d3 = __shfl_sync(0xFFFFFFFFu, d, 3);

    if (lane == 0) {
        float4 p = make_float4(d0 * s0, d1 * s1, d2 * s2, d3 * s3);
        *reinterpret_cast<float4*>(&g_p[base])   = p;
        *reinterpret_cast<float4*>(&g_acc[base]) = p;
    }
}

// K4: round-1 edges: acc1[col] += p0[row]; 1 edge/thread (max warp supply)
__global__ void k_edge1(const int* __restrict__ ei) {
    int e = blockIdx.x * blockDim.x + threadIdx.x;
    if (e < NEDGES) {
        int row = __ldg(&ei[e]);
        int col = __ldg(&ei[NEDGES + e]);
        atomicAdd(&g_acc[col], __ldg(&g_p[row]));
    }
}

// K5: p1 = dis^2 * acc1 ; acc2 init = p1
__global__ void k_pre2() {
    int i = blockIdx.x * blockDim.x + threadIdx.x;
    if (i < NNODES) {
        float dd = g_dis[i];
        float v = dd * dd * g_acc[i];
        g_p2[i]   = v;
        g_acc2[i] = v;
    }
}

// K6: round-2 edges: acc2[col] += p1[row]; 1 edge/thread
__global__ void k_edge2(const int* __restrict__ ei) {
    int e = blockIdx.x * blockDim.x + threadIdx.x;
    if (e < NEDGES) {
        int row = __ldg(&ei[e]);
        int col = __ldg(&ei[NEDGES + e]);
        atomicAdd(&g_acc2[col], __ldg(&g_p2[row]));
    }
}

// K7: out = dis * acc2 + b
__global__ void k_post(float* __restrict__ out, const float* __restrict__ b) {
    int i = blockIdx.x * blockDim.x + threadIdx.x;
    if (i < NNODES) {
        out[i] = g_dis[i] * g_acc2[i] + b[0];
    }
}

extern "C" void kernel_launch(void* const* d_in, const int* in_sizes, int n_in,
                              void* d_out, int out_size) {
    const float* x  = (const float*)d_in[0];
    const int*   ei = (const int*)d_in[1];
    const float* W  = (const float*)d_in[2];
    const float* b  = (const float*)d_in[3];
    float* out = (float*)d_out;

    const int T = 256;
    const int gN   = (NNODES + T - 1) / T;
    const int gE   = (NEDGES + T - 1) / T;        // 1 edge/thread
    const int gE2  = (NEDGES / 2 + T - 1) / T;    // 2 edges/thread
    const int gDot = ((NNODES / 4) * 32 + T - 1) / T;

    k_init<<<gN, T>>>();
    k_count_deg<<<gE2, T>>>(ei);
    k_dot<<<gDot, T>>>(x, W);
    k_edge1<<<gE, T>>>(ei);
    k_pre2<<<gN, T>>>();
    k_edge2<<<gE, T>>>(ei);
    k_post<<<gN, T>>>(out, b);
}